// round 1
// baseline (speedup 1.0000x reference)
#include <cuda_runtime.h>

#define D 64
#define K 1024
#define TILE_ROWS 128
#define TILE_COLS 128
#define NCHUNKS (K / TILE_COLS)

// Scratch (no device allocation allowed)
__device__ float g_codebookT[K * D];   // [K][D] row-major for coalesced gather
__device__ float g_cnorm[K];           // ||m_k||^2
__device__ float g_blocksum[1024];     // per-block loss partials

// ---------------------------------------------------------------------------
// Prep: transpose codebook + code norms. cm is [D][K] row-major.
// ---------------------------------------------------------------------------
__global__ void vq_prep(const float* __restrict__ cm) {
    int k = blockIdx.x * blockDim.x + threadIdx.x;
    if (k >= K) return;
    float s = 0.f;
#pragma unroll 8
    for (int d = 0; d < D; ++d) {
        float v = cm[d * K + k];       // coalesced across k
        g_codebookT[k * D + d] = v;
        s += v * v;                    // same formula/order as reference
    }
    g_cnorm[k] = s;
}

// ---------------------------------------------------------------------------
// Main: per block, 128 samples x full K sweep in 128-col chunks.
// 256 threads, 16x16 grid, 8x8 register micro-tile each.
// ---------------------------------------------------------------------------
__global__ __launch_bounds__(256, 2)
void vq_main(const float* __restrict__ x, const float* __restrict__ cm,
             float* __restrict__ out, float* __restrict__ out_idx)
{
    extern __shared__ float smem_raw[];
    float* Xs      = smem_raw;                 // [64][132]  X tile, transposed, padded
    float* Ms      = Xs + 64 * 132;            // [64][128]  M chunk
    float* xnorm_s = Ms + 64 * 128;            // [128]
    float* redv    = xnorm_s + 128;            // [128][17]
    int*   redi    = (int*)(redv + 128 * 17);  // [128][17]
    float* rsum    = (float*)(redi + 128 * 17);// [256]

    const int tid = threadIdx.x;
    const int tx  = tid & 15;
    const int ty  = tid >> 4;
    const int row0 = blockIdx.x * TILE_ROWS;

    // ---- Load X tile [128 rows x 64 d], store transposed Xs[d][row] ----
    {
        const float4* x4 = (const float4*)(x + (size_t)row0 * D);
#pragma unroll
        for (int i = 0; i < 8; ++i) {
            int e  = tid + 256 * i;      // 0..2047 float4s
            int r  = e >> 4;             // row in tile
            int dg = e & 15;             // which group of 4 dims
            float4 v = x4[r * 16 + dg];
            Xs[(dg * 4 + 0) * 132 + r] = v.x;
            Xs[(dg * 4 + 1) * 132 + r] = v.y;
            Xs[(dg * 4 + 2) * 132 + r] = v.z;
            Xs[(dg * 4 + 3) * 132 + r] = v.w;
        }
    }
    __syncthreads();

    // ---- Row norms ||x||^2 ----
    if (tid < TILE_ROWS) {
        float s = 0.f;
#pragma unroll 8
        for (int d = 0; d < D; ++d) {
            float v = Xs[d * 132 + tid];
            s += v * v;
        }
        xnorm_s[tid] = s;
    }
    __syncthreads();

    float xn[8];
#pragma unroll
    for (int i = 0; i < 8; ++i) xn[i] = xnorm_s[ty * 8 + i];

    float minv[8];
    int   mini[8];
#pragma unroll
    for (int i = 0; i < 8; ++i) { minv[i] = 3.402823466e+38f; mini[i] = 0; }

    // ---- K chunks ----
    for (int c = 0; c < NCHUNKS; ++c) {
        // load M chunk: Ms[d][col] = cm[d*K + c*128 + col]
        {
            const float4* cm4 = (const float4*)cm;
            float4* ms4 = (float4*)Ms;
#pragma unroll
            for (int i = 0; i < 8; ++i) {
                int e  = tid + 256 * i;  // 0..2047 float4s
                int d  = e >> 5;
                int cg = e & 31;
                ms4[d * 32 + cg] = cm4[d * (K / 4) + c * (TILE_COLS / 4) + cg];
            }
        }
        __syncthreads();

        float acc[8][8];
#pragma unroll
        for (int i = 0; i < 8; ++i)
#pragma unroll
            for (int j = 0; j < 8; ++j) acc[i][j] = 0.f;

#pragma unroll 4
        for (int d = 0; d < D; ++d) {
            float4 a0 = *(const float4*)&Xs[d * 132 + ty * 8];
            float4 a1 = *(const float4*)&Xs[d * 132 + ty * 8 + 4];
            float4 b0 = *(const float4*)&Ms[d * 128 + tx * 8];
            float4 b1 = *(const float4*)&Ms[d * 128 + tx * 8 + 4];
            float a[8] = {a0.x, a0.y, a0.z, a0.w, a1.x, a1.y, a1.z, a1.w};
            float b[8] = {b0.x, b0.y, b0.z, b0.w, b1.x, b1.y, b1.z, b1.w};
#pragma unroll
            for (int i = 0; i < 8; ++i)
#pragma unroll
                for (int j = 0; j < 8; ++j)
                    acc[i][j] = fmaf(a[i], b[j], acc[i][j]);
        }

        const int cb = c * TILE_COLS + tx * 8;
        float cn[8];
#pragma unroll
        for (int j = 0; j < 8; ++j) cn[j] = g_cnorm[cb + j];

#pragma unroll
        for (int i = 0; i < 8; ++i) {
#pragma unroll
            for (int j = 0; j < 8; ++j) {
                // match reference rounding: (||x||^2 - 2*p) + ||m||^2
                float dist = (xn[i] - 2.0f * acc[i][j]) + cn[j];
                if (dist < minv[i]) { minv[i] = dist; mini[i] = cb + j; }
            }
        }
        __syncthreads();   // before overwriting Ms
    }

    // ---- argmin reduce across the 16 tx slices ----
#pragma unroll
    for (int i = 0; i < 8; ++i) {
        redv[(ty * 8 + i) * 17 + tx] = minv[i];
        redi[(ty * 8 + i) * 17 + tx] = mini[i];
    }
    __syncthreads();

    float partial = 0.f;
    if (tid < TILE_ROWS) {
        const int row = tid;
        float bv = redv[row * 17];
        int   bi = redi[row * 17];
#pragma unroll
        for (int t = 1; t < 16; ++t) {
            float v  = redv[row * 17 + t];
            int   id = redi[row * 17 + t];
            if (v < bv || (v == bv && id < bi)) { bv = v; bi = id; }
        }
        out_idx[row0 + row] = (float)bi;

        // gather code row (coalesced from transposed codebook) + STE + loss
        const float4* q4 = (const float4*)(g_codebookT + (size_t)bi * D);
        float4* o4 = (float4*)(out + (size_t)(row0 + row) * D);
#pragma unroll
        for (int dg = 0; dg < 16; ++dg) {
            float4 q = q4[dg];
            float xa = Xs[(dg * 4 + 0) * 132 + row];
            float xb = Xs[(dg * 4 + 1) * 132 + row];
            float xc = Xs[(dg * 4 + 2) * 132 + row];
            float xd = Xs[(dg * 4 + 3) * 132 + row];
            float da = q.x - xa, db = q.y - xb, dc = q.z - xc, dd = q.w - xd;
            partial += da * da + db * db + dc * dc + dd * dd;
            float4 o;
            o.x = xa + da; o.y = xb + db; o.z = xc + dc; o.w = xd + dd;  // STE: x + (q - x)
            o4[dg] = o;
        }
    }

    // ---- deterministic block loss reduction ----
    rsum[tid] = partial;
    __syncthreads();
    for (int s = 128; s > 0; s >>= 1) {
        if (tid < s) rsum[tid] += rsum[tid + s];
        __syncthreads();
    }
    if (tid == 0) g_blocksum[blockIdx.x] = rsum[0];
}

// ---------------------------------------------------------------------------
// Final loss: deterministic fixed-order fp64 sum of block partials.
// ---------------------------------------------------------------------------
__global__ void vq_finish(float* __restrict__ out_loss, int nblocks, float inv_total) {
    if (threadIdx.x == 0 && blockIdx.x == 0) {
        double s = 0.0;
        for (int i = 0; i < nblocks; ++i) s += (double)g_blocksum[i];
        float q_loss = (float)(s * (double)inv_total);
        out_loss[0] = q_loss + 0.25f * q_loss;   // q_loss + 0.25*e_loss (identical values)
    }
}

// ---------------------------------------------------------------------------
// Launch: out = [outputs (N*64) | cluster_index as float (N) | loss (1)]
// ---------------------------------------------------------------------------
extern "C" void kernel_launch(void* const* d_in, const int* in_sizes, int n_in,
                              void* d_out, int out_size) {
    const float* x  = (const float*)d_in[0];   // [B,H,W,D] fp32
    const float* cm = (const float*)d_in[1];   // [D,K] fp32
    float* out = (float*)d_out;

    const int N = in_sizes[0] / D;             // 65536
    float* out_idx  = out + (size_t)N * D;
    float* out_loss = out_idx + N;

    const size_t smem_bytes =
        (size_t)(64 * 132 + 64 * 128 + 128 + 128 * 17 + 128 * 17 + 256) * sizeof(float);
    cudaFuncSetAttribute(vq_main, cudaFuncAttributeMaxDynamicSharedMemorySize,
                         (int)smem_bytes);

    vq_prep<<<(K + 255) / 256, 256>>>(cm);

    const int nblocks = N / TILE_ROWS;         // 512
    vq_main<<<nblocks, 256, smem_bytes>>>(x, cm, out, out_idx);

    vq_finish<<<1, 32>>>(out_loss, nblocks, 1.0f / (float)(N * D));
}

// round 3
// speedup vs baseline: 1.1144x; 1.1144x over previous
#include <cuda_runtime.h>
#include <cstdint>
#include <cfloat>

#define Dd 64
#define Kk 1024
#define TR 128
#define NCH 8              // 8 chunks of 128 codes

#define MARGIN 5e-4f

#define NSTRIDE 320        // bytes per code row in smem B (80 words: conflict-free LDS.128)
#define SMB_SPLIT 40960    // 128 rows * 320B
#define SMB_BUF   81920    // 2 splits

// ---------------- smem layout (bytes) ----------------
#define SM_B    0                      // 2 buf x 2 split x 128 x 320 = 163840
#define SM_XS   163840                 // Xs: 128 x 65 floats = 33280
#define SM_CN   197120                 // cnorm 1024 floats = 4096
#define SM_XN   201216                 // xnorm 128 floats = 512
#define SM_RV   201728                 // refine reduce val 256
#define SM_RI   202752                 // refine reduce idx 256
#define SM_BI   203776                 // best index per row, 128 ints
#define SM_RS   204288                 // loss reduce 256
#define SM_NREF 205312                 // refine counter
#define SM_RL   205316                 // refine row list, 128 ints
#define SM_TOTAL 205828

// ---------------- scratch (no allocs allowed) ----------------
__device__ float g_codebookT[Kk*Dd];   // [K][D] exact fp32, for gather + refine
__device__ float g_cnorm[Kk];
__device__ float g_BhiP[Kk*Dd];        // tf32 hi split, [K][D] PERMUTED within 16-d groups
__device__ float g_BloP[Kk*Dd];        // tf32 lo split, permuted
__device__ float g_blocksum[1024];

// ---------------- helpers ----------------
__device__ __forceinline__ uint32_t smem_u32(const void* p){
    uint32_t a; asm("{ .reg .u64 t; cvta.to.shared.u64 t, %1; cvt.u32.u64 %0, t; }" : "=r"(a) : "l"(p)); return a;
}
__device__ __forceinline__ uint32_t f2tf32(float f){
    uint32_t r; asm("cvt.rna.tf32.f32 %0, %1;" : "=r"(r) : "f"(f)); return r;
}
__device__ __forceinline__ float4 lds128(uint32_t a){
    float4 v; asm volatile("ld.shared.v4.f32 {%0,%1,%2,%3}, [%4];"
        : "=f"(v.x),"=f"(v.y),"=f"(v.z),"=f"(v.w) : "r"(a)); return v;
}
#define CP16(dst, src) asm volatile("cp.async.cg.shared.global [%0], [%1], 16;" :: "r"(dst), "l"(src) : "memory")
#define CP_COMMIT()    asm volatile("cp.async.commit_group;" ::: "memory")
#define CP_WAIT(n)     asm volatile("cp.async.wait_group %0;" :: "n"(n) : "memory")

// m16n8k8 tf32 mma (sm_80+ portable; runs on tensor pipe)
#define MMA8(c0,c1,c2,c3, a0,a1,a2,a3, b0,b1) \
  asm volatile("mma.sync.aligned.m16n8k8.row.col.f32.tf32.tf32.f32 " \
    "{%0,%1,%2,%3},{%4,%5,%6,%7},{%8,%9},{%0,%1,%2,%3};" \
    : "+f"(c0),"+f"(c1),"+f"(c2),"+f"(c3) \
    : "r"(a0),"r"(a1),"r"(a2),"r"(a3),"r"(b0),"r"(b1))

#define UPD(bv,bi,bv2, s, idx) do{ float _s=(s); \
    if (_s < (bv)){ (bv2)=(bv); (bv)=_s; (bi)=(idx); } \
    else if (_s < (bv2)) (bv2)=_s; }while(0)

// ---------------------------------------------------------------------------
// Prep: transpose cm[D][K] -> [K][D]; exact copy + tf32 hi/lo splits (permuted
// within each 16-d group so one LDS.128 feeds two mma k-steps) + code norms.
// Permutation: src d = 16g + 4j + l4  ->  dst 16g + 4*l4 + j.
// ---------------------------------------------------------------------------
__global__ void vq_prep(const float* __restrict__ cm){
    __shared__ float tile[64][65];
    const int t  = threadIdx.x;
    const int kb = blockIdx.x * 64;
    const int j  = t & 63;
    const int dr = t >> 6;
#pragma unroll
    for (int i = 0; i < 16; ++i){
        int d = dr + 4*i;
        tile[d][j] = cm[d*Kk + kb + j];          // coalesced over k
    }
    __syncthreads();
#pragma unroll
    for (int i = 0; i < 16; ++i){
        int kr = dr + 4*i;                        // code within block
        int d  = j;                               // dim
        float v = tile[d][kr];
        uint32_t hb = f2tf32(v);
        float hf = __uint_as_float(hb);
        uint32_t lb = f2tf32(v - hf);
        int o  = (kb + kr)*Dd + d;
        int dp = (d & ~15) + (d & 3)*4 + ((d >> 2) & 3);
        int op = (kb + kr)*Dd + dp;
        g_codebookT[o] = v;
        g_BhiP[op] = __uint_as_float(hb);
        g_BloP[op] = __uint_as_float(lb);
    }
    if (t < 64){
        float s = 0.f;
#pragma unroll
        for (int d = 0; d < 64; ++d){ float v = tile[d][t]; s += v*v; }
        g_cnorm[kb + t] = s;
    }
}

// ---------------------------------------------------------------------------
// Main: 3xTF32 mma.sync GEMM + fused argmin (+ exact-refine net) + gather/STE.
// 256 threads = 8 warps; warp w owns rows 16w..16w+15, sweeps all 1024 cols.
// ---------------------------------------------------------------------------
__global__ __launch_bounds__(256, 1)
void vq_main(const float* __restrict__ x, float* __restrict__ out,
             float* __restrict__ out_idx)
{
    extern __shared__ char smem[];
    const uint32_t sb = smem_u32(smem);
    float* Xs      = (float*)(smem + SM_XS);
    float* cn_s    = (float*)(smem + SM_CN);
    float* xn_s    = (float*)(smem + SM_XN);
    float* RV      = (float*)(smem + SM_RV);
    int*   RI      = (int*)  (smem + SM_RI);
    int*   besti_s = (int*)  (smem + SM_BI);
    float* RS      = (float*)(smem + SM_RS);
    int*   nref_p  = (int*)  (smem + SM_NREF);
    int*   reflist = (int*)  (smem + SM_RL);

    const int tid = threadIdx.x;
    const int wid = tid >> 5, lid = tid & 31;
    const int l4  = lid & 3,  gq  = lid >> 2;
    const int row0 = blockIdx.x * TR;

    if (tid == 0) *nref_p = 0;

    // ---- issue cp.async for B chunk 0 (overlaps all the setup below) ----
    {
#pragma unroll
        for (int i = 0; i < 16; ++i){
            int e = tid + 256*i;
            int split = e >> 11, rem = e & 2047, n = rem >> 4, grp = rem & 15;
            const float* sp = split ? g_BloP : g_BhiP;
            uint64_t src; asm("cvta.to.global.u64 %0, %1;" : "=l"(src)
                              : "l"(sp + (size_t)n*Dd + grp*4));
            uint32_t dst = sb + SM_B + split*SMB_SPLIT + (uint32_t)(n*NSTRIDE + grp*16);
            CP16(dst, src);
        }
        CP_COMMIT();
    }

    // ---- load X tile [128 x 64] into Xs (pad 65) + cn_s ----
    {
        const float4* x4 = (const float4*)(x + (size_t)row0 * Dd);
#pragma unroll
        for (int i = 0; i < 8; ++i){
            int e = tid + 256*i;
            int r = e >> 4, g = e & 15;
            float4 v = x4[e];
            Xs[r*65 + g*4 + 0] = v.x; Xs[r*65 + g*4 + 1] = v.y;
            Xs[r*65 + g*4 + 2] = v.z; Xs[r*65 + g*4 + 3] = v.w;
        }
    }
#pragma unroll
    for (int i = 0; i < 4; ++i) cn_s[tid + 256*i] = g_cnorm[tid + 256*i];
    __syncthreads();

    // ---- row norms (for exact refine only) ----
    if (tid < 128){
        float s = 0.f;
#pragma unroll
        for (int d = 0; d < 64; ++d){ float v = Xs[tid*65 + d]; s += v*v; }
        xn_s[tid] = s;
    }

    // ---- A fragments: hi/lo tf32, resident in registers for all 8 chunks ----
    uint32_t Ah[32], Al[32];
    {
        const int r0 = 16*wid + gq, r1 = r0 + 8;
#pragma unroll
        for (int kk = 0; kk < 8; ++kk){
            float v0 = Xs[r0*65 + 8*kk + l4];
            float v1 = Xs[r1*65 + 8*kk + l4];
            float v2 = Xs[r0*65 + 8*kk + 4 + l4];
            float v3 = Xs[r1*65 + 8*kk + 4 + l4];
            uint32_t h;
            h = f2tf32(v0); Ah[kk*4+0] = h; Al[kk*4+0] = f2tf32(v0 - __uint_as_float(h));
            h = f2tf32(v1); Ah[kk*4+1] = h; Al[kk*4+1] = f2tf32(v1 - __uint_as_float(h));
            h = f2tf32(v2); Ah[kk*4+2] = h; Al[kk*4+2] = f2tf32(v2 - __uint_as_float(h));
            h = f2tf32(v3); Ah[kk*4+3] = h; Al[kk*4+3] = f2tf32(v3 - __uint_as_float(h));
        }
    }

    float bv0 = FLT_MAX, bv20 = FLT_MAX, bv1 = FLT_MAX, bv21 = FLT_MAX;
    int   bi0 = 0, bi1 = 0;

    // ---- chunk loop: double-buffered B, tensor GEMM + argmin epilogue ----
    for (int c = 0; c < NCH; ++c){
        if (c + 1 < NCH){
            const int buf = (c + 1) & 1;
#pragma unroll
            for (int i = 0; i < 16; ++i){
                int e = tid + 256*i;
                int split = e >> 11, rem = e & 2047, n = rem >> 4, grp = rem & 15;
                const float* sp = split ? g_BloP : g_BhiP;
                uint64_t src; asm("cvta.to.global.u64 %0, %1;" : "=l"(src)
                                  : "l"(sp + (size_t)((c+1)*128 + n)*Dd + grp*4));
                uint32_t dst = sb + SM_B + buf*SMB_BUF + split*SMB_SPLIT
                             + (uint32_t)(n*NSTRIDE + grp*16);
                CP16(dst, src);
            }
            CP_COMMIT();
            CP_WAIT(1);
        } else {
            CP_WAIT(0);
        }
        __syncthreads();

        const uint32_t bbase = sb + SM_B + (uint32_t)(c & 1) * SMB_BUF;
#pragma unroll
        for (int nt = 0; nt < 16; ++nt){
            const uint32_t nb = bbase + (uint32_t)((nt*8 + gq)*NSTRIDE + l4*16);
            float4 bh[4], bl[4];
#pragma unroll
            for (int p = 0; p < 4; ++p) bh[p] = lds128(nb + p*64);
#pragma unroll
            for (int p = 0; p < 4; ++p) bl[p] = lds128(nb + SMB_SPLIT + p*64);

            float c0 = 0.f, c1 = 0.f, c2 = 0.f, c3 = 0.f;
#pragma unroll
            for (int p = 0; p < 4; ++p){
                MMA8(c0,c1,c2,c3, Ah[8*p+0],Ah[8*p+1],Ah[8*p+2],Ah[8*p+3],
                     __float_as_uint(bh[p].x), __float_as_uint(bh[p].y));
                MMA8(c0,c1,c2,c3, Ah[8*p+4],Ah[8*p+5],Ah[8*p+6],Ah[8*p+7],
                     __float_as_uint(bh[p].z), __float_as_uint(bh[p].w));
            }
#pragma unroll
            for (int p = 0; p < 4; ++p){
                MMA8(c0,c1,c2,c3, Ah[8*p+0],Ah[8*p+1],Ah[8*p+2],Ah[8*p+3],
                     __float_as_uint(bl[p].x), __float_as_uint(bl[p].y));
                MMA8(c0,c1,c2,c3, Ah[8*p+4],Ah[8*p+5],Ah[8*p+6],Ah[8*p+7],
                     __float_as_uint(bl[p].z), __float_as_uint(bl[p].w));
            }
#pragma unroll
            for (int p = 0; p < 4; ++p){
                MMA8(c0,c1,c2,c3, Al[8*p+0],Al[8*p+1],Al[8*p+2],Al[8*p+3],
                     __float_as_uint(bh[p].x), __float_as_uint(bh[p].y));
                MMA8(c0,c1,c2,c3, Al[8*p+4],Al[8*p+5],Al[8*p+6],Al[8*p+7],
                     __float_as_uint(bh[p].z), __float_as_uint(bh[p].w));
            }

            // score = ||m||^2 - 2 x.m  (||x||^2 constant per row; refine is exact)
            const int colb = c*128 + nt*8 + l4*2;
            const float cn0 = cn_s[colb], cn1 = cn_s[colb+1];
            UPD(bv0, bi0, bv20, fmaf(-2.f, c0, cn0), colb);
            UPD(bv0, bi0, bv20, fmaf(-2.f, c1, cn1), colb + 1);
            UPD(bv1, bi1, bv21, fmaf(-2.f, c2, cn0), colb);
            UPD(bv1, bi1, bv21, fmaf(-2.f, c3, cn1), colb + 1);
        }
        __syncthreads();   // all warps done with this buffer before next overwrite
    }

    // ---- reduce argmin across the 4 lanes sharing each row ----
#pragma unroll
    for (int off = 1; off < 4; off <<= 1){
        float ov  = __shfl_xor_sync(~0u, bv0, off);
        int   oi  = __shfl_xor_sync(~0u, bi0, off);
        float ov2 = __shfl_xor_sync(~0u, bv20, off);
        float lose;
        if (ov < bv0 || (ov == bv0 && oi < bi0)){ lose = bv0; bv0 = ov; bi0 = oi; }
        else lose = ov;
        bv20 = fminf(bv20, fminf(ov2, lose));

        ov  = __shfl_xor_sync(~0u, bv1, off);
        oi  = __shfl_xor_sync(~0u, bi1, off);
        ov2 = __shfl_xor_sync(~0u, bv21, off);
        if (ov < bv1 || (ov == bv1 && oi < bi1)){ lose = bv1; bv1 = ov; bi1 = oi; }
        else lose = ov;
        bv21 = fminf(bv21, fminf(ov2, lose));
    }
    if (l4 == 0){
        const int r0 = 16*wid + gq, r1 = r0 + 8;
        besti_s[r0] = bi0;
        besti_s[r1] = bi1;
        if (bv20 - bv0 < MARGIN){ int s = atomicAdd(nref_p, 1); reflist[s] = r0; }
        if (bv21 - bv1 < MARGIN){ int s = atomicAdd(nref_p, 1); reflist[s] = r1; }
    }
    __syncthreads();

    // ---- exact refine for near-tie rows (expected ~0 rows; guarantees R1 semantics) ----
    const int cnt = *nref_p;
    for (int f = 0; f < cnt; ++f){
        const int row = reflist[f];
        const float xnr = xn_s[row];
        float best = FLT_MAX; int bidx = 0;
#pragma unroll
        for (int kc = 0; kc < 4; ++kc){
            const int k = tid*4 + kc;
            float dot = 0.f;
#pragma unroll
            for (int d = 0; d < 64; ++d)
                dot = fmaf(Xs[row*65 + d], g_codebookT[k*Dd + d], dot);
            float sv = (xnr - 2.0f*dot) + cn_s[k];
            if (sv < best){ best = sv; bidx = k; }
        }
        RV[tid] = best; RI[tid] = bidx;
        __syncthreads();
        for (int s = 128; s > 0; s >>= 1){
            if (tid < s){
                float ov = RV[tid+s]; int oi = RI[tid+s];
                if (ov < RV[tid] || (ov == RV[tid] && oi < RI[tid])){ RV[tid] = ov; RI[tid] = oi; }
            }
            __syncthreads();
        }
        if (tid == 0) besti_s[row] = RI[0];
        __syncthreads();
    }

    // ---- gather + STE output + loss partial ----
    float partial = 0.f;
    if (tid < 128){
        const int bi = besti_s[tid];
        out_idx[row0 + tid] = (float)bi;
        const float4* q4 = (const float4*)(g_codebookT + (size_t)bi * Dd);
        float4* o4 = (float4*)(out + (size_t)(row0 + tid) * Dd);
#pragma unroll
        for (int g = 0; g < 16; ++g){
            float4 q = q4[g];
            float xa = Xs[tid*65 + g*4 + 0];
            float xb = Xs[tid*65 + g*4 + 1];
            float xc = Xs[tid*65 + g*4 + 2];
            float xd = Xs[tid*65 + g*4 + 3];
            float da = q.x - xa, db = q.y - xb, dc = q.z - xc, dd = q.w - xd;
            partial += da*da + db*db + dc*dc + dd*dd;
            float4 o; o.x = xa + da; o.y = xb + db; o.z = xc + dc; o.w = xd + dd;
            o4[g] = o;
        }
    }
    RS[tid] = partial;
    __syncthreads();
    for (int s = 128; s > 0; s >>= 1){
        if (tid < s) RS[tid] += RS[tid + s];
        __syncthreads();
    }
    if (tid == 0) g_blocksum[blockIdx.x] = RS[0];
}

// ---------------------------------------------------------------------------
__global__ void vq_finish(float* __restrict__ out_loss, int nblocks, float inv_total){
    if (threadIdx.x == 0 && blockIdx.x == 0){
        double s = 0.0;
        for (int i = 0; i < nblocks; ++i) s += (double)g_blocksum[i];
        float q_loss = (float)(s * (double)inv_total);
        out_loss[0] = q_loss + 0.25f * q_loss;
    }
}

// ---------------------------------------------------------------------------
extern "C" void kernel_launch(void* const* d_in, const int* in_sizes, int n_in,
                              void* d_out, int out_size) {
    const float* x  = (const float*)d_in[0];   // [B,H,W,D] fp32
    const float* cm = (const float*)d_in[1];   // [D,K] fp32
    float* out = (float*)d_out;

    const int N = in_sizes[0] / Dd;            // 65536
    float* out_idx  = out + (size_t)N * Dd;
    float* out_loss = out_idx + N;

    cudaFuncSetAttribute(vq_main, cudaFuncAttributeMaxDynamicSharedMemorySize, SM_TOTAL);

    vq_prep<<<Kk/64, 256>>>(cm);
    vq_main<<<N/TR, 256, SM_TOTAL>>>(x, out, out_idx);
    vq_finish<<<1, 32>>>(out_loss, N/TR, 1.0f / (float)(N * Dd));
}

// round 4
// speedup vs baseline: 1.3612x; 1.2214x over previous
#include <cuda_runtime.h>
#include <cuda_fp16.h>
#include <cstdint>
#include <cfloat>

#define Dd 64
#define Kk 1024
#define TR 128
#define NCH 8

#define MARGIN 1e-3f

#define BPITCH 144                 // bytes per code row in smem (conflict-free)
#define SMB_SPLIT (128*BPITCH)     // 18432
#define SMB_BUF   (2*SMB_SPLIT)    // 36864

// ---------------- smem layout (bytes) ----------------
#define SM_B    0                  // 2 buf x 36864 = 73728
#define SM_XS   73728              // 128 x 65 fp32 = 33280
#define SM_CN   107008             // 4096
#define SM_XN   111104             // 512
#define SM_RV   111616             // 1024
#define SM_RI   112640             // 1024
#define SM_BI   113664             // 512
#define SM_RS   114176             // 1024
#define SM_NREF 115200             // 4
#define SM_RL   115204             // 512
#define SM_TOTAL 115716

// ---------------- scratch ----------------
__device__ float  g_codebookT[Kk*Dd];  // [K][D] exact fp32 (gather + refine)
__device__ float  g_cnorm[Kk];
__device__ __half g_Bh16[Kk*Dd];       // fp16 hi split, permuted rows (128B each)
__device__ __half g_Bl16[Kk*Dd];       // fp16 lo split, permuted
__device__ float  g_blocksum[1024];

// ---------------- helpers ----------------
__device__ __forceinline__ uint32_t smem_u32(const void* p){
    uint32_t a; asm("{ .reg .u64 t; cvta.to.shared.u64 t, %1; cvt.u32.u64 %0, t; }" : "=r"(a) : "l"(p)); return a;
}
__device__ __forceinline__ uint4 lds128(uint32_t a){
    uint4 v; asm volatile("ld.shared.v4.u32 {%0,%1,%2,%3}, [%4];"
        : "=r"(v.x),"=r"(v.y),"=r"(v.z),"=r"(v.w) : "r"(a)); return v;
}
#define CP16(dst, src) asm volatile("cp.async.cg.shared.global [%0], [%1], 16;" :: "r"(dst), "l"(src) : "memory")
#define CP_COMMIT()    asm volatile("cp.async.commit_group;" ::: "memory")
#define CP_WAIT(n)     asm volatile("cp.async.wait_group %0;" :: "n"(n) : "memory")

// fp16 m16n8k16, fp32 accumulate (sm_80+ portable)
#define MMA16(c0,c1,c2,c3, a0,a1,a2,a3, b0,b1) \
  asm volatile("mma.sync.aligned.m16n8k16.row.col.f32.f16.f16.f32 " \
    "{%0,%1,%2,%3},{%4,%5,%6,%7},{%8,%9},{%0,%1,%2,%3};" \
    : "+f"(c0),"+f"(c1),"+f"(c2),"+f"(c3) \
    : "r"(a0),"r"(a1),"r"(a2),"r"(a3),"r"(b0),"r"(b1))

#define UPD(bv,bi,bv2, s, idx) do{ float _s=(s); \
    if (_s < (bv)){ (bv2)=(bv); (bv)=_s; (bi)=(idx); } \
    else if (_s < (bv2)) (bv2)=_s; }while(0)

__device__ __forceinline__ uint32_t packh2(float x, float y){
    __half2 h = __halves2half2(__float2half_rn(x), __float2half_rn(y));
    return *(uint32_t*)&h;
}

// B-row permutation: dim d -> slot so lane t reads its 16 values contiguously.
// slot(d): s=d>>4, r=d&15, t=(r>>1)&3, hi8=(r>>3)&1, sub=r&1
//          slot = t*16 + s*4 + hi8*2 + sub
__device__ __forceinline__ int bslot(int d){
    int s = d >> 4, r = d & 15;
    return ((r >> 1) & 3) * 16 + s * 4 + ((r >> 3) & 1) * 2 + (r & 1);
}

// ---------------------------------------------------------------------------
// Prep: transpose cm[D][K]; exact fp32 copy + fp16 hi/lo splits in permuted
// row layout (staged in smem, coalesced dump) + code norms.
// ---------------------------------------------------------------------------
__global__ void vq_prep(const float* __restrict__ cm){
    __shared__ float  tile[64][65];
    __shared__ __half hst[64*64];
    __shared__ __half lst[64*64];
    const int t  = threadIdx.x;
    const int kb = blockIdx.x * 64;
    const int j  = t & 63;          // dim
    const int dr = t >> 6;
#pragma unroll
    for (int i = 0; i < 16; ++i){
        int d = dr + 4*i;
        tile[d][j] = cm[d*Kk + kb + j];
    }
    __syncthreads();
    const int slot = bslot(j);
#pragma unroll
    for (int i = 0; i < 16; ++i){
        int kr = dr + 4*i;                 // code within block
        float v = tile[j][kr];
        __half h = __float2half_rn(v);
        __half l = __float2half_rn(v - __half2float(h));
        g_codebookT[(kb + kr)*Dd + j] = v;
        hst[kr*64 + slot] = h;
        lst[kr*64 + slot] = l;
    }
    if (t < 64){
        float s = 0.f;
#pragma unroll
        for (int d = 0; d < 64; ++d){ float v = tile[d][t]; s += v*v; }
        g_cnorm[kb + t] = s;
    }
    __syncthreads();
    // coalesced dump: 64 rows x 128B per split = 512 uint4 each
    const uint4* hs4 = (const uint4*)hst;
    const uint4* ls4 = (const uint4*)lst;
    uint4* gh4 = (uint4*)(g_Bh16 + (size_t)kb * Dd);
    uint4* gl4 = (uint4*)(g_Bl16 + (size_t)kb * Dd);
#pragma unroll
    for (int i = 0; i < 2; ++i){
        gh4[t + 256*i] = hs4[t + 256*i];
        gl4[t + 256*i] = ls4[t + 256*i];
    }
}

// ---------------------------------------------------------------------------
// Main: 3x fp16 m16n8k16 split GEMM, 3 independent accumulator chains,
// fused argmin + exact-refine net + gather/STE/loss.
// ---------------------------------------------------------------------------
__global__ __launch_bounds__(256, 1)
void vq_main(const float* __restrict__ x, float* __restrict__ out,
             float* __restrict__ out_idx)
{
    extern __shared__ char smem[];
    const uint32_t sb = smem_u32(smem);
    float* Xs      = (float*)(smem + SM_XS);
    float* cn_s    = (float*)(smem + SM_CN);
    float* xn_s    = (float*)(smem + SM_XN);
    float* RV      = (float*)(smem + SM_RV);
    int*   RI      = (int*)  (smem + SM_RI);
    int*   besti_s = (int*)  (smem + SM_BI);
    float* RS      = (float*)(smem + SM_RS);
    int*   nref_p  = (int*)  (smem + SM_NREF);
    int*   reflist = (int*)  (smem + SM_RL);

    const int tid = threadIdx.x;
    const int wid = tid >> 5, lid = tid & 31;
    const int l4  = lid & 3,  gq  = lid >> 2;
    const int row0 = blockIdx.x * TR;

    if (tid == 0) *nref_p = 0;

    // ---- cp.async B chunk 0 (2048 x 16B: hi+lo) ----
#pragma unroll
    for (int i = 0; i < 8; ++i){
        int e = tid + 256*i;
        int split = e >> 10, rem = e & 1023, n = rem >> 3, grp = rem & 7;
        const __half* sp = split ? g_Bl16 : g_Bh16;
        uint64_t src; asm("cvta.to.global.u64 %0, %1;" : "=l"(src)
                          : "l"(sp + (size_t)n*Dd + grp*8));
        uint32_t dst = sb + SM_B + split*SMB_SPLIT + (uint32_t)(n*BPITCH + grp*16);
        CP16(dst, src);
    }
    CP_COMMIT();

    // ---- X tile -> Xs (pad 65) + cn_s ----
    {
        const float4* x4 = (const float4*)(x + (size_t)row0 * Dd);
#pragma unroll
        for (int i = 0; i < 8; ++i){
            int e = tid + 256*i;
            int r = e >> 4, g = e & 15;
            float4 v = x4[e];
            Xs[r*65 + g*4 + 0] = v.x; Xs[r*65 + g*4 + 1] = v.y;
            Xs[r*65 + g*4 + 2] = v.z; Xs[r*65 + g*4 + 3] = v.w;
        }
    }
#pragma unroll
    for (int i = 0; i < 4; ++i) cn_s[tid + 256*i] = g_cnorm[tid + 256*i];
    __syncthreads();

    if (tid < 128){
        float s = 0.f;
#pragma unroll
        for (int d = 0; d < 64; ++d){ float v = Xs[tid*65 + d]; s += v*v; }
        xn_s[tid] = s;
    }

    // ---- A fragments: fp16 hi/lo, resident for all chunks ----
    // step s regs: a0=(r0; k=16s+2t,+1) a1=(r1) a2=(r0; k=16s+2t+8,+9) a3=(r1)
    uint32_t Ah[16], Al[16];
    {
        const int r0 = 16*wid + gq, r1 = r0 + 8;
#pragma unroll
        for (int s = 0; s < 4; ++s){
#pragma unroll
            for (int p = 0; p < 2; ++p){
                int k0 = 16*s + 2*l4 + 8*p;
                float u0 = Xs[r0*65 + k0], u1 = Xs[r0*65 + k0 + 1];
                float w0 = Xs[r1*65 + k0], w1 = Xs[r1*65 + k0 + 1];
                __half hu0 = __float2half_rn(u0), hu1 = __float2half_rn(u1);
                __half hw0 = __float2half_rn(w0), hw1 = __float2half_rn(w1);
                __half2 hh;
                hh = __halves2half2(hu0, hu1); Ah[s*4 + p*2 + 0] = *(uint32_t*)&hh;
                hh = __halves2half2(hw0, hw1); Ah[s*4 + p*2 + 1] = *(uint32_t*)&hh;
                hh = __halves2half2(__float2half_rn(u0 - __half2float(hu0)),
                                    __float2half_rn(u1 - __half2float(hu1)));
                Al[s*4 + p*2 + 0] = *(uint32_t*)&hh;
                hh = __halves2half2(__float2half_rn(w0 - __half2float(hw0)),
                                    __float2half_rn(w1 - __half2float(hw1)));
                Al[s*4 + p*2 + 1] = *(uint32_t*)&hh;
            }
        }
    }

    float bv0 = FLT_MAX, bv20 = FLT_MAX, bv1 = FLT_MAX, bv21 = FLT_MAX;
    int   bi0 = 0, bi1 = 0;

    for (int c = 0; c < NCH; ++c){
        if (c + 1 < NCH){
            const int buf = (c + 1) & 1;
#pragma unroll
            for (int i = 0; i < 8; ++i){
                int e = tid + 256*i;
                int split = e >> 10, rem = e & 1023, n = rem >> 3, grp = rem & 7;
                const __half* sp = split ? g_Bl16 : g_Bh16;
                uint64_t src; asm("cvta.to.global.u64 %0, %1;" : "=l"(src)
                                  : "l"(sp + (size_t)((c+1)*128 + n)*Dd + grp*8));
                uint32_t dst = sb + SM_B + buf*SMB_BUF + split*SMB_SPLIT
                             + (uint32_t)(n*BPITCH + grp*16);
                CP16(dst, src);
            }
            CP_COMMIT();
            CP_WAIT(1);
        } else {
            CP_WAIT(0);
        }
        __syncthreads();

        const uint32_t bbase = sb + SM_B + (uint32_t)(c & 1) * SMB_BUF
                             + (uint32_t)(gq * BPITCH + l4 * 32);
#pragma unroll
        for (int nt = 0; nt < 16; ++nt){
            const uint32_t nb = bbase + (uint32_t)(nt * 8 * BPITCH);
            uint4 bh0 = lds128(nb);
            uint4 bh1 = lds128(nb + 16);
            uint4 bl0 = lds128(nb + SMB_SPLIT);
            uint4 bl1 = lds128(nb + SMB_SPLIT + 16);
            uint32_t bhw[8] = {bh0.x,bh0.y,bh0.z,bh0.w, bh1.x,bh1.y,bh1.z,bh1.w};
            uint32_t blw[8] = {bl0.x,bl0.y,bl0.z,bl0.w, bl1.x,bl1.y,bl1.z,bl1.w};

            // 3 independent accumulator chains (hi*hi, hi*lo, lo*hi)
            float h0=0,h1=0,h2=0,h3=0, u0=0,u1=0,u2=0,u3=0, e0=0,e1=0,e2=0,e3=0;
#pragma unroll
            for (int s = 0; s < 4; ++s){
                MMA16(h0,h1,h2,h3, Ah[s*4+0],Ah[s*4+1],Ah[s*4+2],Ah[s*4+3], bhw[s*2], bhw[s*2+1]);
                MMA16(u0,u1,u2,u3, Ah[s*4+0],Ah[s*4+1],Ah[s*4+2],Ah[s*4+3], blw[s*2], blw[s*2+1]);
                MMA16(e0,e1,e2,e3, Al[s*4+0],Al[s*4+1],Al[s*4+2],Al[s*4+3], bhw[s*2], bhw[s*2+1]);
            }
            float c0 = h0 + (u0 + e0);
            float c1 = h1 + (u1 + e1);
            float c2 = h2 + (u2 + e2);
            float c3 = h3 + (u3 + e3);

            const int colb = c*128 + nt*8 + l4*2;
            const float cn0 = cn_s[colb], cn1 = cn_s[colb+1];
            UPD(bv0, bi0, bv20, fmaf(-2.f, c0, cn0), colb);
            UPD(bv0, bi0, bv20, fmaf(-2.f, c1, cn1), colb + 1);
            UPD(bv1, bi1, bv21, fmaf(-2.f, c2, cn0), colb);
            UPD(bv1, bi1, bv21, fmaf(-2.f, c3, cn1), colb + 1);
        }
        __syncthreads();
    }

    // ---- reduce argmin across the 4 lanes sharing each row ----
#pragma unroll
    for (int off = 1; off < 4; off <<= 1){
        float ov  = __shfl_xor_sync(~0u, bv0, off);
        int   oi  = __shfl_xor_sync(~0u, bi0, off);
        float ov2 = __shfl_xor_sync(~0u, bv20, off);
        float lose;
        if (ov < bv0 || (ov == bv0 && oi < bi0)){ lose = bv0; bv0 = ov; bi0 = oi; }
        else lose = ov;
        bv20 = fminf(bv20, fminf(ov2, lose));

        ov  = __shfl_xor_sync(~0u, bv1, off);
        oi  = __shfl_xor_sync(~0u, bi1, off);
        ov2 = __shfl_xor_sync(~0u, bv21, off);
        if (ov < bv1 || (ov == bv1 && oi < bi1)){ lose = bv1; bv1 = ov; bi1 = oi; }
        else lose = ov;
        bv21 = fminf(bv21, fminf(ov2, lose));
    }
    if (l4 == 0){
        const int r0 = 16*wid + gq, r1 = r0 + 8;
        besti_s[r0] = bi0;
        besti_s[r1] = bi1;
        if (bv20 - bv0 < MARGIN){ int s = atomicAdd(nref_p, 1); reflist[s] = r0; }
        if (bv21 - bv1 < MARGIN){ int s = atomicAdd(nref_p, 1); reflist[s] = r1; }
    }
    __syncthreads();

    // ---- exact refine for near-tie rows (guarantees R1 fp32 semantics) ----
    const int cnt = *nref_p;
    for (int f = 0; f < cnt; ++f){
        const int row = reflist[f];
        const float xnr = xn_s[row];
        float best = FLT_MAX; int bidx = 0;
#pragma unroll
        for (int kc = 0; kc < 4; ++kc){
            const int k = tid*4 + kc;
            float dot = 0.f;
#pragma unroll
            for (int d = 0; d < 64; ++d)
                dot = fmaf(Xs[row*65 + d], g_codebookT[k*Dd + d], dot);
            float sv = (xnr - 2.0f*dot) + cn_s[k];
            if (sv < best){ best = sv; bidx = k; }
        }
        RV[tid] = best; RI[tid] = bidx;
        __syncthreads();
        for (int s = 128; s > 0; s >>= 1){
            if (tid < s){
                float ov = RV[tid+s]; int oi = RI[tid+s];
                if (ov < RV[tid] || (ov == RV[tid] && oi < RI[tid])){ RV[tid] = ov; RI[tid] = oi; }
            }
            __syncthreads();
        }
        if (tid == 0) besti_s[row] = RI[0];
        __syncthreads();
    }

    // ---- gather + STE output + loss partial ----
    float partial = 0.f;
    if (tid < 128){
        const int bi = besti_s[tid];
        out_idx[row0 + tid] = (float)bi;
        const float4* q4 = (const float4*)(g_codebookT + (size_t)bi * Dd);
        float4* o4 = (float4*)(out + (size_t)(row0 + tid) * Dd);
#pragma unroll
        for (int g = 0; g < 16; ++g){
            float4 q = q4[g];
            float xa = Xs[tid*65 + g*4 + 0];
            float xb = Xs[tid*65 + g*4 + 1];
            float xc = Xs[tid*65 + g*4 + 2];
            float xd = Xs[tid*65 + g*4 + 3];
            float da = q.x - xa, db = q.y - xb, dc = q.z - xc, dd = q.w - xd;
            partial += da*da + db*db + dc*dc + dd*dd;
            float4 o; o.x = xa + da; o.y = xb + db; o.z = xc + dc; o.w = xd + dd;
            o4[g] = o;
        }
    }
    RS[tid] = partial;
    __syncthreads();
    for (int s = 128; s > 0; s >>= 1){
        if (tid < s) RS[tid] += RS[tid + s];
        __syncthreads();
    }
    if (tid == 0) g_blocksum[blockIdx.x] = RS[0];
}

// ---------------------------------------------------------------------------
__global__ void vq_finish(float* __restrict__ out_loss, int nblocks, float inv_total){
    if (threadIdx.x == 0 && blockIdx.x == 0){
        double s = 0.0;
        for (int i = 0; i < nblocks; ++i) s += (double)g_blocksum[i];
        float q_loss = (float)(s * (double)inv_total);
        out_loss[0] = q_loss + 0.25f * q_loss;
    }
}

// ---------------------------------------------------------------------------
extern "C" void kernel_launch(void* const* d_in, const int* in_sizes, int n_in,
                              void* d_out, int out_size) {
    const float* x  = (const float*)d_in[0];
    const float* cm = (const float*)d_in[1];
    float* out = (float*)d_out;

    const int N = in_sizes[0] / Dd;
    float* out_idx  = out + (size_t)N * Dd;
    float* out_loss = out_idx + N;

    cudaFuncSetAttribute(vq_main, cudaFuncAttributeMaxDynamicSharedMemorySize, SM_TOTAL);

    vq_prep<<<Kk/64, 256>>>(cm);
    vq_main<<<N/TR, 256, SM_TOTAL>>>(x, out, out_idx);
    vq_finish<<<1, 32>>>(out_loss, N/TR, 1.0f / (float)(N * Dd));
}